// round 1
// baseline (speedup 1.0000x reference)
#include <cuda_runtime.h>

// LFQ quantizer, factorized softmax formulation.
// N = 8192 samples, D = 14 dims, K = 16384 codes.
//
// p_j = prod_d sigmoid(400 * x_d * c_jd)   (exact factorization of softmax(s/T))
// sample entropy   = sum_d binary_entropy(sigmoid(400 x_d))
// avg_probs[h*128+l] = (1/N) sum_i phi_i[h] * plo_i[l]   -> 128x128 outer-product GEMM

#define DIMS 14
#define SPB 64            // samples per block in main kernel
#define NCODES 16384

__device__ float g_M[NCODES];   // un-normalized sum of probs over samples
__device__ float g_commit;     // sum of (x - q)^2
__device__ float g_sampH;      // sum of per-sample entropies

__global__ void lfq_zero_kernel() {
    int i = blockIdx.x * blockDim.x + threadIdx.x;
    if (i < NCODES) g_M[i] = 0.f;
    if (i == 0) { g_commit = 0.f; g_sampH = 0.f; }
}

__global__ __launch_bounds__(256) void lfq_main_kernel(const float* __restrict__ x,
                                                       float* __restrict__ out) {
    __shared__ float qp[SPB][DIMS];    // P(bit=1) per sample/dim, computed stably
    __shared__ float qm[SPB][DIMS];    // P(bit=0)
    __shared__ float s_plo[8][128];
    __shared__ float s_phi[8][128];
    __shared__ float red[256];

    const int tid = threadIdx.x;
    const int s0 = blockIdx.x * SPB;

    float commit_acc = 0.f;
    float h_acc = 0.f;

    // ---- per-element pass: sign output, commit loss, sample entropy, per-dim probs ----
    for (int e = tid; e < SPB * DIMS; e += 256) {
        int gi = s0 * DIMS + e;
        float xv = x[gi];
        float qz = (xv > 0.f) ? 1.f : -1.f;
        out[gi] = qz;
        float dq = xv - qz;
        commit_acc += dq * dq;

        float z = 400.f * xv;             // 2 * (logits/T coefficient)
        float t = fabsf(z);
        float u = expf(-t);               // <= 1, no overflow
        float inv = 1.f / (1.f + u);
        // stable binary entropy of sigmoid(z): log(1+u) + t*u/(1+u)
        h_acc += log1pf(u) + t * u * inv;

        float qbig = inv;                 // sigmoid(|z|)
        float qsml = u * inv;             // sigmoid(-|z|), no cancellation
        int s = e / DIMS, d = e - s * DIMS;
        if (z >= 0.f) { qp[s][d] = qbig; qm[s][d] = qsml; }
        else          { qp[s][d] = qsml; qm[s][d] = qbig; }
    }

    // ---- block-reduce commit & entropy partials ----
    red[tid] = commit_acc;
    __syncthreads();
    for (int off = 128; off; off >>= 1) {
        if (tid < off) red[tid] += red[tid + off];
        __syncthreads();
    }
    if (tid == 0) atomicAdd(&g_commit, red[0]);
    __syncthreads();
    red[tid] = h_acc;
    __syncthreads();
    for (int off = 128; off; off >>= 1) {
        if (tid < off) red[tid] += red[tid + off];
        __syncthreads();
    }
    if (tid == 0) atomicAdd(&g_sampH, red[0]);

    // ---- outer-product accumulation: M[h][l] += phi_i[h] * plo_i[l] ----
    float acc[8][8];
    #pragma unroll
    for (int r = 0; r < 8; ++r)
        #pragma unroll
        for (int c = 0; c < 8; ++c)
            acc[r][c] = 0.f;

    const int tr = tid >> 4;   // 0..15  (hi rows, strided by 16)
    const int tc = tid & 15;   // 0..15  (lo cols, strided by 16)

    for (int ch = 0; ch < SPB / 8; ++ch) {
        __syncthreads();
        // build plo/phi for 8 samples: 2048 entries, 256 threads, 8 iters
        for (int k2 = tid; k2 < 2048; k2 += 256) {
            int which = k2 >> 10;          // 0 = plo (bits 0..6), 1 = phi (bits 7..13)
            int s = (k2 >> 7) & 7;
            int e = k2 & 127;
            int base = ch * 8 + s;
            const float* qpb = which ? &qp[base][7] : &qp[base][0];
            const float* qmb = which ? &qm[base][7] : &qm[base][0];
            float p = 1.f;
            #pragma unroll
            for (int d = 0; d < 7; ++d)
                p *= ((e >> d) & 1) ? qpb[d] : qmb[d];
            if (which) s_phi[s][e] = p; else s_plo[s][e] = p;
        }
        __syncthreads();
        #pragma unroll
        for (int s = 0; s < 8; ++s) {
            float ph[8], pl[8];
            #pragma unroll
            for (int r = 0; r < 8; ++r) ph[r] = s_phi[s][tr + 16 * r];
            #pragma unroll
            for (int c = 0; c < 8; ++c) pl[c] = s_plo[s][tc + 16 * c];
            #pragma unroll
            for (int r = 0; r < 8; ++r)
                #pragma unroll
                for (int c = 0; c < 8; ++c)
                    acc[r][c] += ph[r] * pl[c];
        }
    }

    #pragma unroll
    for (int r = 0; r < 8; ++r)
        #pragma unroll
        for (int c = 0; c < 8; ++c)
            atomicAdd(&g_M[(tr + 16 * r) * 128 + (tc + 16 * c)], acc[r][c]);
}

__global__ void lfq_final_kernel(float* __restrict__ out, int qn, int out_size, float n_samples) {
    __shared__ float red[256];
    int tid = threadIdx.x;
    const float invN = 1.f / n_samples;
    float acc = 0.f;
    for (int i = tid; i < NCODES; i += 256) {
        float m = g_M[i] * invN;
        acc -= m * logf(m + 1e-5f);
    }
    red[tid] = acc;
    __syncthreads();
    for (int off = 128; off; off >>= 1) {
        if (tid < off) red[tid] += red[tid + off];
        __syncthreads();
    }
    if (tid == 0 && out_size >= qn + 4) {
        float avg_e = red[0];
        float samp_e = g_sampH * invN;
        float commit = g_commit / (n_samples * (float)DIMS);
        out[qn + 0] = samp_e - avg_e;   // entropy_aux_loss (weights 1.0/1.0)
        out[qn + 1] = samp_e;           // sample_entropy
        out[qn + 2] = avg_e;            // avg_entropy
        out[qn + 3] = commit;           // commit_loss
    }
}

extern "C" void kernel_launch(void* const* d_in, const int* in_sizes, int n_in,
                              void* d_out, int out_size) {
    const float* x = (const float*)d_in[0];
    float* out = (float*)d_out;
    int qn = in_sizes[0];              // 8*1024*14 = 114688 elements of q_out
    int n_samples = qn / DIMS;         // 8192
    int nblk = n_samples / SPB;        // 128

    lfq_zero_kernel<<<(NCODES + 255) / 256, 256>>>();
    lfq_main_kernel<<<nblk, 256>>>(x, out);
    lfq_final_kernel<<<1, 256>>>(out, qn, out_size, (float)n_samples);
}